// round 10
// baseline (speedup 1.0000x reference)
#include <cuda_runtime.h>
#include <cuda.h>
#include <cstdint>
#include <cstddef>

// ============================================================================
// Arch gate: tcgen05 is arch-SPECIFIC (sm_103a). The harness also builds a
// plain compute_103 PTX pass where these mnemonics are illegal — compile an
// empty body there. Only the sm_103a SASS pass gets the real kernel.
// ============================================================================
#if defined(__CUDA_ARCH_FEAT_SM103_ALL) || defined(__CUDA_ARCH_FEAT_SM100_ALL) || \
    (defined(__CUDA_ARCH_SPECIFIC__) && (__CUDA_ARCH_SPECIFIC__ >= 1000)) || \
    (defined(__CUDA_ARCH_FAMILY_SPECIFIC__) && (__CUDA_ARCH_FAMILY_SPECIFIC__ >= 1000))
#define KAN_HAS_TCGEN05 1
#else
#define KAN_HAS_TCGEN05 0
#endif

// ============================================================================
// PTX helpers
// ============================================================================
__device__ __forceinline__ uint32_t smem_u32(const void* p) {
    uint32_t a;
    asm("{ .reg .u64 t; cvta.to.shared.u64 t, %1; cvt.u32.u64 %0, t; }"
        : "=r"(a) : "l"(p));
    return a;
}
__device__ __forceinline__ uint32_t elect_one() {
    uint32_t r;
    asm volatile("{\n\t.reg .pred p;\n\telect.sync _|p, 0xFFFFFFFF;\n\t"
                 "selp.b32 %0, 1, 0, p;\n\t}" : "=r"(r));
    return r;
}
__device__ __forceinline__ uint32_t cluster_rank() {
    uint32_t r;
    asm("mov.u32 %0, %%cluster_ctarank;" : "=r"(r));
    return r;
}

#define MBARRIER_INIT(addr, cnt) \
    asm volatile("mbarrier.init.shared.b64 [%0], %1;" \
                 :: "r"((uint32_t)(addr)), "r"((uint32_t)(cnt)) : "memory")

// Arrive on the mbarrier at the same SMEM offset in cluster CTA `rank`.
#define MBARRIER_ARRIVE_CLUSTER(local_addr, rank) \
    asm volatile( \
        "{\n\t.reg .b32 remAddr;\n\t" \
        "mapa.shared::cluster.u32 remAddr, %0, %1;\n\t" \
        "mbarrier.arrive.shared::cluster.b64 _, [remAddr];\n\t}" \
        :: "r"((uint32_t)(local_addr)), "r"((uint32_t)(rank)) : "memory")

#define MBARRIER_EXPECT_TX(addr, tx) \
    asm volatile("mbarrier.arrive.expect_tx.shared.b64 _, [%0], %1;" \
                 :: "r"((uint32_t)(addr)), "r"((uint32_t)(tx)) : "memory")

#define MBARRIER_WAIT_PARITY(mbar_smem_addr, phase_parity) do { \
    uint32_t _mbar = (uint32_t)(mbar_smem_addr); \
    uint32_t _parity = (uint32_t)(phase_parity); \
    uint32_t _done; \
    asm volatile( \
        "{\n\t.reg .pred p;\n\t" \
        "mbarrier.try_wait.parity.acquire.cta.shared::cta.b64 p, [%1], %2;\n\t" \
        "selp.b32 %0, 1, 0, p;\n\t}" \
        : "=r"(_done) : "r"(_mbar), "r"(_parity) : "memory"); \
    if (!_done) { \
        asm volatile( \
            "{\n\t.reg .pred P1;\n\t" \
            "WAIT_LOOP_%=:\n\t" \
            "mbarrier.try_wait.parity.acquire.cta.shared::cta.b64 P1, [%0], %1, 0x989680;\n\t" \
            "@P1 bra.uni WAIT_DONE_%=;\n\t" \
            "bra.uni WAIT_LOOP_%=;\n\t" \
            "WAIT_DONE_%=:\n\t}" \
            :: "r"(_mbar), "r"(_parity) : "memory"); \
    } \
} while(0)

#define MBARRIER_WAIT_PARITY_RELAXED(mbar_smem_addr, phase_parity) do { \
    uint32_t _mbar = (uint32_t)(mbar_smem_addr); \
    uint32_t _parity = (uint32_t)(phase_parity); \
    uint32_t _done; \
    asm volatile( \
        "{\n\t.reg .pred p;\n\t" \
        "mbarrier.try_wait.parity.relaxed.cta.shared::cta.b64 p, [%1], %2, 0x989680;\n\t" \
        "selp.b32 %0, 1, 0, p;\n\t}" \
        : "=r"(_done) : "r"(_mbar), "r"(_parity) : "memory"); \
    if (!_done) { \
        asm volatile( \
            "{\n\t.reg .pred P1;\n\t" \
            "WAIT_LOOP_%=:\n\t" \
            "mbarrier.try_wait.parity.relaxed.cta.shared::cta.b64 P1, [%0], %1, 0x989680;\n\t" \
            "@P1 bra.uni WAIT_DONE_%=;\n\t" \
            "bra.uni WAIT_LOOP_%=;\n\t" \
            "WAIT_DONE_%=:\n\t}" \
            :: "r"(_mbar), "r"(_parity) : "memory"); \
    } \
} while(0)

// cta_group::2 TMA load: both CTAs execute; complete_tx targets the LEADER
// CTA's barrier (bit 24 of the barrier address cleared).
#define TMA_LOAD_3D_CG2(smem_addr, tensor_map, cx, cy, cz, mbar) \
    asm volatile( \
        "{\n\t.reg .b32 leaderBar;\n\t" \
        "and.b32 leaderBar, %5, 0xFEFFFFFF;\n\t" \
        "cp.async.bulk.tensor.3d.cta_group::2.shared::cluster.global" \
        ".tile.mbarrier::complete_tx::bytes [%0], [%1, {%2, %3, %4}], [leaderBar];\n\t}" \
        :: "r"((uint32_t)(smem_addr)), "l"(tensor_map), \
           "r"((int32_t)(cx)), "r"((int32_t)(cy)), "r"((int32_t)(cz)), \
           "r"((uint32_t)(mbar)) : "memory")

#define CLUSTER_SYNC() do { \
    asm volatile("barrier.cluster.arrive.aligned;" ::: "memory"); \
    asm volatile("barrier.cluster.wait.aligned;" ::: "memory"); \
} while(0)

#if KAN_HAS_TCGEN05
#define TCGEN05_ALLOC_CG2(smem_result_addr, nCols) \
    asm volatile("tcgen05.alloc.cta_group::2.sync.aligned.shared::cta.b32 [%0], %1;" \
                 :: "r"((uint32_t)(smem_result_addr)), "r"((uint32_t)(nCols)) : "memory")
#define TCGEN05_DEALLOC_CG2(tmem_addr, nCols) \
    asm volatile("tcgen05.dealloc.cta_group::2.sync.aligned.b32 %0, %1;" \
                 :: "r"(tmem_addr), "r"((uint32_t)(nCols)))
#define TCGEN05_RELINQUISH_CG2() \
    asm volatile("tcgen05.relinquish_alloc_permit.cta_group::2.sync.aligned;")
#define TCGEN05_COMMIT_MC_CG2(mbar_smem_addr, mask) \
    asm volatile("tcgen05.commit.cta_group::2.mbarrier::arrive::one.shared::cluster.multicast::cluster.b64 [%0], %1;" \
                 :: "r"((uint32_t)(mbar_smem_addr)), "h"((uint16_t)(mask)) : "memory")
#define TCGEN05_WAIT_LD() \
    asm volatile("tcgen05.wait::ld.sync.aligned;" ::: "memory")
#define TCGEN05_WAIT_ST() \
    asm volatile("tcgen05.wait::st.sync.aligned;" ::: "memory")
#define TCGEN05_FENCE_BEFORE() \
    asm volatile("tcgen05.fence::before_thread_sync;" ::: "memory")
#define TCGEN05_FENCE_AFTER() \
    asm volatile("tcgen05.fence::after_thread_sync;" ::: "memory")

#define TCGEN05_ST_32X32B_X16(tmem_addr, r) \
    asm volatile( \
        "tcgen05.st.sync.aligned.32x32b.x16.b32 [%0], " \
        "{%1, %2, %3, %4, %5, %6, %7, %8, " \
        " %9, %10, %11, %12, %13, %14, %15, %16};" \
        :: "r"(tmem_addr), \
           "r"((r)[0]),  "r"((r)[1]),  "r"((r)[2]),  "r"((r)[3]), \
           "r"((r)[4]),  "r"((r)[5]),  "r"((r)[6]),  "r"((r)[7]), \
           "r"((r)[8]),  "r"((r)[9]),  "r"((r)[10]), "r"((r)[11]), \
           "r"((r)[12]), "r"((r)[13]), "r"((r)[14]), "r"((r)[15]) \
        : "memory")

#define TCGEN05_LD_32X32B_X32(r, tmem_addr) \
    asm volatile( \
        "tcgen05.ld.sync.aligned.32x32b.x32.b32 " \
        "{%0, %1, %2, %3, %4, %5, %6, %7, " \
        " %8, %9, %10, %11, %12, %13, %14, %15, " \
        " %16, %17, %18, %19, %20, %21, %22, %23, " \
        " %24, %25, %26, %27, %28, %29, %30, %31}, [%32];" \
        : "=r"((r)[0]),  "=r"((r)[1]),  "=r"((r)[2]),  "=r"((r)[3]), \
          "=r"((r)[4]),  "=r"((r)[5]),  "=r"((r)[6]),  "=r"((r)[7]), \
          "=r"((r)[8]),  "=r"((r)[9]),  "=r"((r)[10]), "=r"((r)[11]), \
          "=r"((r)[12]), "=r"((r)[13]), "=r"((r)[14]), "=r"((r)[15]), \
          "=r"((r)[16]), "=r"((r)[17]), "=r"((r)[18]), "=r"((r)[19]), \
          "=r"((r)[20]), "=r"((r)[21]), "=r"((r)[22]), "=r"((r)[23]), \
          "=r"((r)[24]), "=r"((r)[25]), "=r"((r)[26]), "=r"((r)[27]), \
          "=r"((r)[28]), "=r"((r)[29]), "=r"((r)[30]), "=r"((r)[31]) \
        : "r"(tmem_addr))

// tf32 TS MMA, cta_group::2 (M=256 across the pair, A in TMEM). K=8/dispatch.
__device__ __forceinline__ void mma_tf32_ts_cg2(uint32_t d_tmem, uint32_t a_tmem,
                                                uint64_t b_desc, uint32_t idesc, bool acc) {
    uint32_t en = acc ? 1u : 0u;
    asm volatile(
        "{\n\t.reg .pred p;\n\t"
        "setp.ne.u32 p, %5, 0;\n\t"
        "tcgen05.mma.cta_group::2.kind::tf32 [%0], [%1], %2, %3, "
        "{%4, %4, %4, %4, %4, %4, %4, %4}, p;\n\t}"
        :: "r"(d_tmem), "r"(a_tmem), "l"(b_desc), "r"(idesc), "r"(0u), "r"(en)
        : "memory");
}
#endif  // KAN_HAS_TCGEN05

static constexpr uint64_t SMEM_DESC_BASE_SW128 =
    (uint64_t(2) << 61) | (uint64_t(1) << 46) | (uint64_t(64) << 32) | (uint64_t(1) << 16);
#define MAKE_SMEM_DESC(base_addr) \
    (SMEM_DESC_BASE_SW128 | ((uint64_t)((base_addr) >> 4) & 0x3FFF))

// ============================================================================
// Fused kernel v5: basis written DIRECTLY to TMEM (TS-mode MMA) + cg2 GEMM.
// SMEM now carries B only (64 B/cyc vs 128 B/cyc crossbar) — A bypasses the
// crossbar via the TMEM write port. TMEM: D cols 0-255, A ring cols 256-447.
// Warps 0-15: basis -> TMEM A. Warp 16: TMA B half. Warp 17 (rank0): MMA.
// ============================================================================
static constexpr int TILE_M   = 128;   // per CTA
static constexpr int TILE_N   = 256;   // per cluster (N/2 = 128 per CTA)
static constexpr int KCHUNK   = 32;
static constexpr int NK       = 4096 / KCHUNK;    // 128 MMA chunks
static constexpr int NSUP     = NK / 2;           // 64 A superstages (64 K-cols)
static constexpr int ASTAGES  = 3;                // TMEM A ring depth
static constexpr int BSTAGES  = 8;
static constexpr int B_ST     = 128 * 128;        // 16 KB per B stage (N/2 rows)
static constexpr int TMEM_D   = 0;                // cols 0..255
static constexpr int TMEM_A   = 256;              // cols 256..(256+3*64)

// smem map (byte offsets)
static constexpr int SM_TMEMP  = 0;
static constexpr int SM_FULLA  = 8;                        // 3 x 8B
static constexpr int SM_EMPTYA = SM_FULLA  + ASTAGES * 8;
static constexpr int SM_FULLB  = SM_EMPTYA + ASTAGES * 8;  // 8 x 8B
static constexpr int SM_EMPTYB = SM_FULLB  + BSTAGES * 8;
static constexpr int SM_DONE   = SM_EMPTYB + BSTAGES * 8;
static constexpr int SM_B      = 1024;
static constexpr int SMEM_TOTAL = SM_B + BSTAGES * B_ST;   // 132096

// idesc cg2: c=F32(1<<4), a=TF32(2<<7), b=TF32(2<<10), N=256 (32<<17), M=256 (16<<24)
static constexpr uint32_t IDESC2 =
    (16u << 24) | (32u << 17) | (2u << 10) | (2u << 7) | (1u << 4);

static constexpr int NCOMPUTE_WARPS = 16;
static constexpr int NTHREADS = (NCOMPUTE_WARPS + 2) * 32;  // 576
static constexpr uint16_t MC_MASK = 0x3;

__global__ void __launch_bounds__(NTHREADS, 1) __cluster_dims__(2, 1, 1)
kan_fused_kernel(const float* __restrict__ x,
                 const __grid_constant__ CUtensorMap tma_b,
                 float* __restrict__ out)
{
#if KAN_HAS_TCGEN05
    extern __shared__ __align__(1024) char smem[];
    uint32_t sb = smem_u32(smem);
    int tid = threadIdx.x;
    int wid = tid >> 5, lid = tid & 31;
    int m0 = blockIdx.x * TILE_M;          // per-CTA M origin (pairs share n0)
    int n0 = blockIdx.y * TILE_N;
    uint32_t rank = cluster_rank();        // == blockIdx.x & 1

    if (tid == 0) {
#pragma unroll
        for (int s = 0; s < ASTAGES; s++) {
            MBARRIER_INIT(sb + SM_FULLA  + s * 8, 2 * NCOMPUTE_WARPS); // 1/warp/CTA
            MBARRIER_INIT(sb + SM_EMPTYA + s * 8, 1);    // MC commit, local wait
        }
#pragma unroll
        for (int s = 0; s < BSTAGES; s++) {
            MBARRIER_INIT(sb + SM_FULLB  + s * 8, 1);    // leader expect_tx 32KB
            MBARRIER_INIT(sb + SM_EMPTYB + s * 8, 1);    // MC commit, local wait
        }
        MBARRIER_INIT(sb + SM_DONE, 1);
    }
    if (wid == 17) TCGEN05_ALLOC_CG2(sb + SM_TMEMP, 512);
    __syncthreads();
    CLUSTER_SYNC();   // barriers + alloc visible cluster-wide before traffic
    uint32_t tmem;
    asm volatile("ld.shared.b32 %0, [%1];" : "=r"(tmem) : "r"(sb + SM_TMEMP));

    if (wid < NCOMPUTE_WARPS) {
        // ======== Basis compute warps: write A straight into TMEM ========
        // warp w: lane-subpartition p = w&3 (rows p*32+lid), feature pair
        // fp = w>>2 -> features {2fp, 2fp+1} of the 8 per superstage.
        // Within a superstage, feature f lands at TMEM cols (f>>2)*32+(f&3)*8,
        // so pair 2fp,2fp+1 = 16 CONTIGUOUS cols at fp*16. One x16 store.
        int p  = wid & 3;
        int fp = wid >> 2;
        int row = p * 32 + lid;
        const float* xrow = x + (size_t)(m0 + row) * 512 + fp * 2;
        uint32_t warp_off = (uint32_t)p << 21;
        uint32_t abase = tmem + TMEM_A + (uint32_t)fp * 16 + warp_off;

        const float c6 = 1.0f / 6.0f;
        const float L2E2 = 2.8853900817779268f;     // 2*log2(e)
        int sa = 0, pha = 1;
        for (int ks = 0; ks < NSUP; ks++) {
            float2 xv = *reinterpret_cast<const float2*>(xrow + ks * 8);
            MBARRIER_WAIT_PARITY(sb + SM_EMPTYA + sa * 8, pha);
            uint32_t r[16];
#pragma unroll
            for (int e = 0; e < 2; e++) {
                float xe = e ? xv.y : xv.x;
                float t, rr;
                asm("ex2.approx.f32 %0, %1;" : "=f"(t) : "f"(xe * L2E2));
                asm("rcp.approx.f32 %0, %1;" : "=f"(rr) : "f"(t + 1.0f));
                float xn = fmaf(-2.0f, rr, 1.0f);   // tanh, err ~1e-7
                float u = (xn + 1.0f) * 5.5f;       // in [0, 11]
                int j = (int)u;
                if (j > 10) j = 10;
                float f = u - (float)j;
                float f2 = f * f, f3 = f2 * f;
                float omf = 1.0f - f;
                float w0 = omf * omf * omf * c6;
                float w1 = (3.0f * f3 - 6.0f * f2 + 4.0f) * c6;
                float w2 = (-3.0f * f3 + 3.0f * f2 + 3.0f * f + 1.0f) * c6;
                float w3 = f3 * c6;
                int b0 = j - 3;
#pragma unroll
                for (int k = 0; k < 8; k++) {
                    int tsel = k - b0;
                    float v = (tsel == 0) ? w0 : (tsel == 1) ? w1 :
                              (tsel == 2) ? w2 : (tsel == 3) ? w3 : 0.0f;
                    asm("cvt.rna.tf32.f32 %0, %1;" : "=r"(r[e * 8 + k]) : "f"(v));
                }
            }
            TCGEN05_ST_32X32B_X16(abase + (uint32_t)sa * 64, r);
            TCGEN05_WAIT_ST();
            TCGEN05_FENCE_BEFORE();
            __syncwarp();
            if (elect_one())
                MBARRIER_ARRIVE_CLUSTER(sb + SM_FULLA + sa * 8, 0);  // leader's fullA
            if (++sa == ASTAGES) { sa = 0; pha ^= 1; }
        }
    } else if (wid == NCOMPUTE_WARPS) {
        // ============ TMA producer: each CTA loads its N/2 B half ============
        if (elect_one()) {
            int s = 0, ph = 1;
            int ncoord = n0 + (int)rank * 128;
            for (int kt = 0; kt < NK; kt++) {
                MBARRIER_WAIT_PARITY_RELAXED(sb + SM_EMPTYB + s * 8, ph);
                if (rank == 0)
                    MBARRIER_EXPECT_TX(sb + SM_FULLB + s * 8, 2 * B_ST);  // both halves
                TMA_LOAD_3D_CG2(sb + SM_B + s * B_ST, &tma_b,
                                kt * KCHUNK, ncoord, 0, sb + SM_FULLB + s * 8);
                if (++s == BSTAGES) { s = 0; ph ^= 1; }
            }
        }
    } else if (rank == 0) {
        // ============ MMA issue warp (leader only) ============
        if (elect_one()) {
            int sa = 0, pa = 0, sbg = 0, pb = 0;
            for (int kt = 0; kt < NK; kt++) {
                if ((kt & 1) == 0) {
                    MBARRIER_WAIT_PARITY(sb + SM_FULLA + sa * 8, pa);
                    TCGEN05_FENCE_AFTER();
                }
                MBARRIER_WAIT_PARITY(sb + SM_FULLB + sbg * 8, pb);
                uint32_t at = tmem + TMEM_A + (uint32_t)sa * 64 + (kt & 1) * 32;
                uint64_t bd = MAKE_SMEM_DESC(sb + SM_B + sbg * B_ST);
#pragma unroll
                for (int j = 0; j < 4; j++)
                    mma_tf32_ts_cg2(tmem + TMEM_D, at + j * 8, bd + 2 * j,
                                    IDESC2, (kt > 0) || (j > 0));
                TCGEN05_COMMIT_MC_CG2(sb + SM_EMPTYB + sbg * 8, MC_MASK);
                if (kt & 1) {
                    TCGEN05_COMMIT_MC_CG2(sb + SM_EMPTYA + sa * 8, MC_MASK);
                    if (++sa == ASTAGES) { sa = 0; pa ^= 1; }
                }
                if (++sbg == BSTAGES) { sbg = 0; pb ^= 1; }
            }
            TCGEN05_COMMIT_MC_CG2(sb + SM_DONE, MC_MASK);
        }
    }

    __syncthreads();
    MBARRIER_WAIT_PARITY(sb + SM_DONE, 0);
    TCGEN05_FENCE_AFTER();

    // ---- Epilogue: 8 warps. Warp w: rows (w&3)*32+lid, cols (w>>2)*128.. ----
    if (wid < 8) {
        int coloff = (wid >> 2) * 128;
        float* orow = out + (size_t)(m0 + (wid & 3) * 32 + lid) * 512 + n0 + coloff;
        for (int cb = 0; cb < 128; cb += 32) {
            uint32_t r[32];
            TCGEN05_LD_32X32B_X32(r, tmem + TMEM_D + coloff + cb);
            TCGEN05_WAIT_LD();
#pragma unroll
            for (int c = 0; c < 32; c += 4) {
                float4 v = make_float4(__uint_as_float(r[c]),     __uint_as_float(r[c + 1]),
                                       __uint_as_float(r[c + 2]), __uint_as_float(r[c + 3]));
                *reinterpret_cast<float4*>(orow + cb + c) = v;
            }
        }
    }

    __syncthreads();
    if (wid == 17) {
        TCGEN05_RELINQUISH_CG2();
        TCGEN05_DEALLOC_CG2(tmem, 512);
    }
    CLUSTER_SYNC();   // no CTA exits while peer ops may target its smem/TMEM
#else
    // compute_103 (non-'a') PTX fallback pass: never executed on sm_103a.
    (void)x; (void)tma_b; (void)out;
#endif
}

// ============================================================================
// Host launcher
// ============================================================================
typedef CUresult (*PFN_encodeTiled)(
    CUtensorMap*, CUtensorMapDataType, cuuint32_t, void*,
    const cuuint64_t*, const cuuint64_t*, const cuuint32_t*, const cuuint32_t*,
    CUtensorMapInterleave, CUtensorMapSwizzle, CUtensorMapL2promotion,
    CUtensorMapFloatOOBfill);

extern "C" void kernel_launch(void* const* d_in, const int* in_sizes, int n_in,
                              void* d_out, int out_size) {
    (void)in_sizes; (void)n_in; (void)out_size;
    const float* x = (const float*)d_in[0];
    void* coeffs   = (void*)d_in[1];
    float* out     = (float*)d_out;

    const int B = 8192, O = 512, K = 4096;

    PFN_encodeTiled enc = nullptr;
    cudaDriverEntryPointQueryResult qres;
    cudaGetDriverEntryPointByVersion("cuTensorMapEncodeTiled", (void**)&enc, 12000,
                                     cudaEnableDefault, &qres);

    CUtensorMap tB;
    {
        cuuint64_t dims[3] = {(cuuint64_t)K, (cuuint64_t)O, 1};
        cuuint64_t str[2]  = {(cuuint64_t)K * 4, (cuuint64_t)K * (cuuint64_t)O * 4};
        cuuint32_t box[3]  = {32, 128, 1};   // per-CTA B half: 128 N-rows
        cuuint32_t es[3]   = {1, 1, 1};
        enc(&tB, CU_TENSOR_MAP_DATA_TYPE_FLOAT32, 3, coeffs, dims, str, box, es,
            CU_TENSOR_MAP_INTERLEAVE_NONE, CU_TENSOR_MAP_SWIZZLE_128B,
            CU_TENSOR_MAP_L2_PROMOTION_L2_128B, CU_TENSOR_MAP_FLOAT_OOB_FILL_NONE);
    }

    cudaFuncSetAttribute(kan_fused_kernel,
                         cudaFuncAttributeMaxDynamicSharedMemorySize, SMEM_TOTAL);
    kan_fused_kernel<<<dim3(B / TILE_M, O / TILE_N, 1), NTHREADS, SMEM_TOTAL>>>(x, tB, out);
}

// round 11
// speedup vs baseline: 3.4964x; 3.4964x over previous
#include <cuda_runtime.h>
#include <cuda.h>
#include <cstdint>
#include <cstddef>

// ============================================================================
// Arch gate: tcgen05 is arch-SPECIFIC (sm_103a). The harness also builds a
// plain compute_103 PTX pass where these mnemonics are illegal — compile an
// empty body there. Only the sm_103a SASS pass gets the real kernel.
// ============================================================================
#if defined(__CUDA_ARCH_FEAT_SM103_ALL) || defined(__CUDA_ARCH_FEAT_SM100_ALL) || \
    (defined(__CUDA_ARCH_SPECIFIC__) && (__CUDA_ARCH_SPECIFIC__ >= 1000)) || \
    (defined(__CUDA_ARCH_FAMILY_SPECIFIC__) && (__CUDA_ARCH_FAMILY_SPECIFIC__ >= 1000))
#define KAN_HAS_TCGEN05 1
#else
#define KAN_HAS_TCGEN05 0
#endif

// ============================================================================
// PTX helpers
// ============================================================================
__device__ __forceinline__ uint32_t smem_u32(const void* p) {
    uint32_t a;
    asm("{ .reg .u64 t; cvta.to.shared.u64 t, %1; cvt.u32.u64 %0, t; }"
        : "=r"(a) : "l"(p));
    return a;
}
__device__ __forceinline__ uint32_t elect_one() {
    uint32_t r;
    asm volatile("{\n\t.reg .pred p;\n\telect.sync _|p, 0xFFFFFFFF;\n\t"
                 "selp.b32 %0, 1, 0, p;\n\t}" : "=r"(r));
    return r;
}
__device__ __forceinline__ uint32_t cluster_rank() {
    uint32_t r;
    asm("mov.u32 %0, %%cluster_ctarank;" : "=r"(r));
    return r;
}

#define MBARRIER_INIT(addr, cnt) \
    asm volatile("mbarrier.init.shared.b64 [%0], %1;" \
                 :: "r"((uint32_t)(addr)), "r"((uint32_t)(cnt)) : "memory")

// Arrive on the mbarrier at the same SMEM offset in cluster CTA `rank`.
#define MBARRIER_ARRIVE_CLUSTER(local_addr, rank) \
    asm volatile( \
        "{\n\t.reg .b32 remAddr;\n\t" \
        "mapa.shared::cluster.u32 remAddr, %0, %1;\n\t" \
        "mbarrier.arrive.shared::cluster.b64 _, [remAddr];\n\t}" \
        :: "r"((uint32_t)(local_addr)), "r"((uint32_t)(rank)) : "memory")

#define MBARRIER_EXPECT_TX(addr, tx) \
    asm volatile("mbarrier.arrive.expect_tx.shared.b64 _, [%0], %1;" \
                 :: "r"((uint32_t)(addr)), "r"((uint32_t)(tx)) : "memory")

#define MBARRIER_WAIT_PARITY(mbar_smem_addr, phase_parity) do { \
    uint32_t _mbar = (uint32_t)(mbar_smem_addr); \
    uint32_t _parity = (uint32_t)(phase_parity); \
    uint32_t _done; \
    asm volatile( \
        "{\n\t.reg .pred p;\n\t" \
        "mbarrier.try_wait.parity.acquire.cta.shared::cta.b64 p, [%1], %2;\n\t" \
        "selp.b32 %0, 1, 0, p;\n\t}" \
        : "=r"(_done) : "r"(_mbar), "r"(_parity) : "memory"); \
    if (!_done) { \
        asm volatile( \
            "{\n\t.reg .pred P1;\n\t" \
            "WAIT_LOOP_%=:\n\t" \
            "mbarrier.try_wait.parity.acquire.cta.shared::cta.b64 P1, [%0], %1, 0x989680;\n\t" \
            "@P1 bra.uni WAIT_DONE_%=;\n\t" \
            "bra.uni WAIT_LOOP_%=;\n\t" \
            "WAIT_DONE_%=:\n\t}" \
            :: "r"(_mbar), "r"(_parity) : "memory"); \
    } \
} while(0)

#define MBARRIER_WAIT_PARITY_RELAXED(mbar_smem_addr, phase_parity) do { \
    uint32_t _mbar = (uint32_t)(mbar_smem_addr); \
    uint32_t _parity = (uint32_t)(phase_parity); \
    uint32_t _done; \
    asm volatile( \
        "{\n\t.reg .pred p;\n\t" \
        "mbarrier.try_wait.parity.relaxed.cta.shared::cta.b64 p, [%1], %2, 0x989680;\n\t" \
        "selp.b32 %0, 1, 0, p;\n\t}" \
        : "=r"(_done) : "r"(_mbar), "r"(_parity) : "memory"); \
    if (!_done) { \
        asm volatile( \
            "{\n\t.reg .pred P1;\n\t" \
            "WAIT_LOOP_%=:\n\t" \
            "mbarrier.try_wait.parity.relaxed.cta.shared::cta.b64 P1, [%0], %1, 0x989680;\n\t" \
            "@P1 bra.uni WAIT_DONE_%=;\n\t" \
            "bra.uni WAIT_LOOP_%=;\n\t" \
            "WAIT_DONE_%=:\n\t}" \
            :: "r"(_mbar), "r"(_parity) : "memory"); \
    } \
} while(0)

// cta_group::2 TMA load: both CTAs execute; complete_tx targets the LEADER
// CTA's barrier (bit 24 of the barrier address cleared).
#define TMA_LOAD_3D_CG2(smem_addr, tensor_map, cx, cy, cz, mbar) \
    asm volatile( \
        "{\n\t.reg .b32 leaderBar;\n\t" \
        "and.b32 leaderBar, %5, 0xFEFFFFFF;\n\t" \
        "cp.async.bulk.tensor.3d.cta_group::2.shared::cluster.global" \
        ".tile.mbarrier::complete_tx::bytes [%0], [%1, {%2, %3, %4}], [leaderBar];\n\t}" \
        :: "r"((uint32_t)(smem_addr)), "l"(tensor_map), \
           "r"((int32_t)(cx)), "r"((int32_t)(cy)), "r"((int32_t)(cz)), \
           "r"((uint32_t)(mbar)) : "memory")

#define STS128Z(addr) \
    asm volatile("st.shared.v4.b32 [%0], {%1, %1, %1, %1};" \
                 :: "r"((uint32_t)(addr)), "r"(0u) : "memory")
#define STS32(addr, v) \
    asm volatile("st.shared.b32 [%0], %1;" \
                 :: "r"((uint32_t)(addr)), "r"((uint32_t)(v)) : "memory")
#define FENCE_PROXY_ASYNC() \
    asm volatile("fence.proxy.async.shared::cta;" ::: "memory")
#define CLUSTER_SYNC() do { \
    asm volatile("barrier.cluster.arrive.aligned;" ::: "memory"); \
    asm volatile("barrier.cluster.wait.aligned;" ::: "memory"); \
} while(0)

#if KAN_HAS_TCGEN05
#define TCGEN05_ALLOC_CG2(smem_result_addr, nCols) \
    asm volatile("tcgen05.alloc.cta_group::2.sync.aligned.shared::cta.b32 [%0], %1;" \
                 :: "r"((uint32_t)(smem_result_addr)), "r"((uint32_t)(nCols)) : "memory")
#define TCGEN05_DEALLOC_CG2(tmem_addr, nCols) \
    asm volatile("tcgen05.dealloc.cta_group::2.sync.aligned.b32 %0, %1;" \
                 :: "r"(tmem_addr), "r"((uint32_t)(nCols)))
#define TCGEN05_RELINQUISH_CG2() \
    asm volatile("tcgen05.relinquish_alloc_permit.cta_group::2.sync.aligned;")
#define TCGEN05_COMMIT_MC_CG2(mbar_smem_addr, mask) \
    asm volatile("tcgen05.commit.cta_group::2.mbarrier::arrive::one.shared::cluster.multicast::cluster.b64 [%0], %1;" \
                 :: "r"((uint32_t)(mbar_smem_addr)), "h"((uint16_t)(mask)) : "memory")
#define TCGEN05_WAIT_LD() \
    asm volatile("tcgen05.wait::ld.sync.aligned;" ::: "memory")
#define TCGEN05_FENCE_AFTER() \
    asm volatile("tcgen05.fence::after_thread_sync;" ::: "memory")

#define TCGEN05_LD_32X32B_X32(r, tmem_addr) \
    asm volatile( \
        "tcgen05.ld.sync.aligned.32x32b.x32.b32 " \
        "{%0, %1, %2, %3, %4, %5, %6, %7, " \
        " %8, %9, %10, %11, %12, %13, %14, %15, " \
        " %16, %17, %18, %19, %20, %21, %22, %23, " \
        " %24, %25, %26, %27, %28, %29, %30, %31}, [%32];" \
        : "=r"((r)[0]),  "=r"((r)[1]),  "=r"((r)[2]),  "=r"((r)[3]), \
          "=r"((r)[4]),  "=r"((r)[5]),  "=r"((r)[6]),  "=r"((r)[7]), \
          "=r"((r)[8]),  "=r"((r)[9]),  "=r"((r)[10]), "=r"((r)[11]), \
          "=r"((r)[12]), "=r"((r)[13]), "=r"((r)[14]), "=r"((r)[15]), \
          "=r"((r)[16]), "=r"((r)[17]), "=r"((r)[18]), "=r"((r)[19]), \
          "=r"((r)[20]), "=r"((r)[21]), "=r"((r)[22]), "=r"((r)[23]), \
          "=r"((r)[24]), "=r"((r)[25]), "=r"((r)[26]), "=r"((r)[27]), \
          "=r"((r)[28]), "=r"((r)[29]), "=r"((r)[30]), "=r"((r)[31]) \
        : "r"(tmem_addr))

// tf32 SS MMA, cta_group::2 (M=256 across the pair). K=8 per dispatch.
__device__ __forceinline__ void mma_tf32_ss_cg2(uint32_t d_tmem, uint64_t a_desc,
                                                uint64_t b_desc, uint32_t idesc, bool acc) {
    uint32_t en = acc ? 1u : 0u;
    asm volatile(
        "{\n\t.reg .pred p;\n\t"
        "setp.ne.u32 p, %5, 0;\n\t"
        "tcgen05.mma.cta_group::2.kind::tf32 [%0], %1, %2, %3, "
        "{%4, %4, %4, %4, %4, %4, %4, %4}, p;\n\t}"
        :: "r"(d_tmem), "l"(a_desc), "l"(b_desc), "r"(idesc), "r"(0u), "r"(en)
        : "memory");
}
#endif  // KAN_HAS_TCGEN05

static constexpr uint64_t SMEM_DESC_BASE_SW128 =
    (uint64_t(2) << 61) | (uint64_t(1) << 46) | (uint64_t(64) << 32) | (uint64_t(1) << 16);
#define MAKE_SMEM_DESC(base_addr) \
    (SMEM_DESC_BASE_SW128 | ((uint64_t)((base_addr) >> 4) & 0x3FFF))

// ============================================================================
// Fused kernel v6 (= R8/R9 SS-mode base + ELECTED mbarrier waits).
// Cluster of 2 CTAs covers M=256 x N=256 via cta_group::2; B split N/2 per CTA.
// Warps 0-15: basis -> SMEM A stages (scatter stores). One elected thread per
// warp performs the emptyA wait; __syncwarp broadcasts (waiter count 512->16).
// Warp 16: TMA B half. Warp 17 (rank0): MMA issue.
// ============================================================================
static constexpr int TILE_M   = 128;   // per CTA
static constexpr int TILE_N   = 256;   // per cluster (N/2 = 128 per CTA)
static constexpr int KCHUNK   = 32;
static constexpr int NK       = 4096 / KCHUNK;    // 128 MMA chunks
static constexpr int NSUP     = NK / 2;           // 64 A superstages
static constexpr int ASTAGES  = 3;
static constexpr int BSTAGES  = 6;
static constexpr int A_SUB    = TILE_M * 128;     // 16 KB per 32-col subtile
static constexpr int A_ST2    = 2 * A_SUB;        // 32 KB superstage
static constexpr int B_ST     = 128 * 128;        // 16 KB per B stage (N/2 rows)

// smem map (byte offsets)
static constexpr int SM_TMEMP  = 0;
static constexpr int SM_FULLA  = 8;                        // 3 x 8B
static constexpr int SM_EMPTYA = SM_FULLA  + ASTAGES * 8;
static constexpr int SM_FULLB  = SM_EMPTYA + ASTAGES * 8;  // 6 x 8B
static constexpr int SM_EMPTYB = SM_FULLB  + BSTAGES * 8;
static constexpr int SM_DONE   = SM_EMPTYB + BSTAGES * 8;
static constexpr int SM_A      = 1024;
static constexpr int SM_B      = SM_A + ASTAGES * A_ST2;   // 99328
static constexpr int SMEM_TOTAL = SM_B + BSTAGES * B_ST;   // 197632

// idesc cg2: c=F32(1<<4), a=TF32(2<<7), b=TF32(2<<10), N=256 (32<<17), M=256 (16<<24)
static constexpr uint32_t IDESC2 =
    (16u << 24) | (32u << 17) | (2u << 10) | (2u << 7) | (1u << 4);

static constexpr int NCOMPUTE_WARPS = 16;
static constexpr int NTHREADS = (NCOMPUTE_WARPS + 2) * 32;  // 576
static constexpr uint16_t MC_MASK = 0x3;

__global__ void __launch_bounds__(NTHREADS, 1) __cluster_dims__(2, 1, 1)
kan_fused_kernel(const float* __restrict__ x,
                 const __grid_constant__ CUtensorMap tma_b,
                 float* __restrict__ out)
{
#if KAN_HAS_TCGEN05
    extern __shared__ __align__(1024) char smem[];
    uint32_t sb = smem_u32(smem);
    int tid = threadIdx.x;
    int wid = tid >> 5, lid = tid & 31;
    int m0 = blockIdx.x * TILE_M;          // per-CTA M origin (pairs share n0)
    int n0 = blockIdx.y * TILE_N;
    uint32_t rank = cluster_rank();        // == blockIdx.x & 1

    if (tid == 0) {
#pragma unroll
        for (int s = 0; s < ASTAGES; s++) {
            MBARRIER_INIT(sb + SM_FULLA  + s * 8, 2 * NCOMPUTE_WARPS); // 1/warp/CTA
            MBARRIER_INIT(sb + SM_EMPTYA + s * 8, 1);    // MC commit, local wait
        }
#pragma unroll
        for (int s = 0; s < BSTAGES; s++) {
            MBARRIER_INIT(sb + SM_FULLB  + s * 8, 1);    // leader expect_tx 32KB
            MBARRIER_INIT(sb + SM_EMPTYB + s * 8, 1);    // MC commit, local wait
        }
        MBARRIER_INIT(sb + SM_DONE, 1);
    }
    if (wid == 17) TCGEN05_ALLOC_CG2(sb + SM_TMEMP, 256);
    __syncthreads();
    CLUSTER_SYNC();   // barriers + alloc visible cluster-wide before traffic
    uint32_t tmem;
    asm volatile("ld.shared.b32 %0, [%1];" : "=r"(tmem) : "r"(sb + SM_TMEMP));

    if (wid < NCOMPUTE_WARPS) {
        // ============ Basis compute warps: fill local A superstages ============
        // 512 threads; thread t: row = t>>2 (0..127), fq = t&3 ->
        // features {2fq, 2fq+1} of the 8 per superstage (subtile = fq>>1).
        int row = tid >> 2;
        int fq  = tid & 3;
        const float* xrow = x + (size_t)(m0 + row) * 512 + fq * 2;
        uint32_t xorc = (uint32_t)(row & 7) << 4;   // SW128 per-row XOR
        uint32_t x16  = xorc & 0x10;
        uint32_t xhi  = xorc & 0x60;
        uint32_t tb = sb + SM_A + (uint32_t)(fq >> 1) * A_SUB + (uint32_t)row * 128;
        uint32_t cb0 = (uint32_t)(fq & 1) * 64;
        uint32_t zb[2] = { tb + (cb0 ^ xhi), tb + ((cb0 + 32) ^ xhi) };

        const float c6 = 1.0f / 6.0f;
        const float L2E2 = 2.8853900817779268f;     // 2*log2(e)
        int sa = 0, pha = 1;
        for (int ks = 0; ks < NSUP; ks++) {
            float2 xv = *reinterpret_cast<const float2*>(xrow + ks * 8);
            // Elected wait (per warp, not per thread) -> syncwarp broadcast.
            // The elected acquire + __syncwarp orders the warp's STS below
            // after the consumer's release-arrive (standard CUTLASS pattern).
            if (elect_one())
                MBARRIER_WAIT_PARITY(sb + SM_EMPTYA + sa * 8, pha);
            __syncwarp();
            uint32_t soff = (uint32_t)sa * A_ST2;
#pragma unroll
            for (int e = 0; e < 2; e++) {
                float xe = e ? xv.y : xv.x;
                float t, rr;
                asm("ex2.approx.f32 %0, %1;" : "=f"(t) : "f"(xe * L2E2));
                asm("rcp.approx.f32 %0, %1;" : "=f"(rr) : "f"(t + 1.0f));
                float xn = fmaf(-2.0f, rr, 1.0f);   // tanh, err ~1e-7
                float u = (xn + 1.0f) * 5.5f;       // in [0, 11]
                int j = (int)u;
                if (j > 10) j = 10;
                float f = u - (float)j;
                float f2 = f * f, f3 = f2 * f;
                float omf = 1.0f - f;
                uint32_t w[4];
                asm("cvt.rna.tf32.f32 %0, %1;" : "=r"(w[0]) : "f"(omf * omf * omf * c6));
                asm("cvt.rna.tf32.f32 %0, %1;" : "=r"(w[1]) : "f"((3.0f * f3 - 6.0f * f2 + 4.0f) * c6));
                asm("cvt.rna.tf32.f32 %0, %1;" : "=r"(w[2]) : "f"((-3.0f * f3 + 3.0f * f2 + 3.0f * f + 1.0f) * c6));
                asm("cvt.rna.tf32.f32 %0, %1;" : "=r"(w[3]) : "f"(f3 * c6));
                uint32_t zbe = zb[e] + soff;
                STS128Z(zbe + x16);
                STS128Z(zbe + (16u ^ x16));
                int b0 = j - 3;
#pragma unroll
                for (int t4 = 0; t4 < 4; t4++) {
                    int idx = b0 + t4;
                    if ((unsigned)idx < 8u)
                        STS32(zbe + (((uint32_t)idx * 4) ^ x16), w[t4]);
                }
            }
            FENCE_PROXY_ASYNC();
            __syncwarp();
            if (elect_one())
                MBARRIER_ARRIVE_CLUSTER(sb + SM_FULLA + sa * 8, 0);  // leader's fullA
            if (++sa == ASTAGES) { sa = 0; pha ^= 1; }
        }
    } else if (wid == NCOMPUTE_WARPS) {
        // ============ TMA producer: each CTA loads its N/2 B half ============
        if (elect_one()) {
            int s = 0, ph = 1;
            int ncoord = n0 + (int)rank * 128;
            for (int kt = 0; kt < NK; kt++) {
                MBARRIER_WAIT_PARITY_RELAXED(sb + SM_EMPTYB + s * 8, ph);
                if (rank == 0)
                    MBARRIER_EXPECT_TX(sb + SM_FULLB + s * 8, 2 * B_ST);  // both halves
                TMA_LOAD_3D_CG2(sb + SM_B + s * B_ST, &tma_b,
                                kt * KCHUNK, ncoord, 0, sb + SM_FULLB + s * 8);
                if (++s == BSTAGES) { s = 0; ph ^= 1; }
            }
        }
    } else if (rank == 0) {
        // ============ MMA issue warp (leader only) ============
        if (elect_one()) {
            int sa = 0, pa = 0, sbg = 0, pb = 0;
            for (int kt = 0; kt < NK; kt++) {
                if ((kt & 1) == 0) MBARRIER_WAIT_PARITY(sb + SM_FULLA + sa * 8, pa);
                MBARRIER_WAIT_PARITY(sb + SM_FULLB + sbg * 8, pb);
                uint64_t ad = MAKE_SMEM_DESC(sb + SM_A + sa * A_ST2 + (kt & 1) * A_SUB);
                uint64_t bd = MAKE_SMEM_DESC(sb + SM_B + sbg * B_ST);
#pragma unroll
                for (int j = 0; j < 4; j++)
                    mma_tf32_ss_cg2(tmem, ad + 2 * j, bd + 2 * j, IDESC2, (kt > 0) || (j > 0));
                TCGEN05_COMMIT_MC_CG2(sb + SM_EMPTYB + sbg * 8, MC_MASK);
                if (kt & 1) {
                    TCGEN05_COMMIT_MC_CG2(sb + SM_EMPTYA + sa * 8, MC_MASK);
                    if (++sa == ASTAGES) { sa = 0; pa ^= 1; }
                }
                if (++sbg == BSTAGES) { sbg = 0; pb ^= 1; }
            }
            TCGEN05_COMMIT_MC_CG2(sb + SM_DONE, MC_MASK);
        }
    }

    __syncthreads();
    MBARRIER_WAIT_PARITY(sb + SM_DONE, 0);
    TCGEN05_FENCE_AFTER();

    // ---- Epilogue: 8 warps. Warp w: rows (w&3)*32+lid, cols (w>>2)*128.. ----
    if (wid < 8) {
        int coloff = (wid >> 2) * 128;
        float* orow = out + (size_t)(m0 + (wid & 3) * 32 + lid) * 512 + n0 + coloff;
        for (int cb = 0; cb < 128; cb += 32) {
            uint32_t r[32];
            TCGEN05_LD_32X32B_X32(r, tmem + coloff + cb);
            TCGEN05_WAIT_LD();
#pragma unroll
            for (int c = 0; c < 32; c += 4) {
                float4 v = make_float4(__uint_as_float(r[c]),     __uint_as_float(r[c + 1]),
                                       __uint_as_float(r[c + 2]), __uint_as_float(r[c + 3]));
                *reinterpret_cast<float4*>(orow + cb + c) = v;
            }
        }
    }

    __syncthreads();
    if (wid == 17) {
        TCGEN05_RELINQUISH_CG2();
        TCGEN05_DEALLOC_CG2(tmem, 256);
    }
    CLUSTER_SYNC();   // no CTA exits while peer ops may target its smem/TMEM
#else
    // compute_103 (non-'a') PTX fallback pass: never executed on sm_103a.
    (void)x; (void)tma_b; (void)out;
#endif
}

// ============================================================================
// Host launcher
// ============================================================================
typedef CUresult (*PFN_encodeTiled)(
    CUtensorMap*, CUtensorMapDataType, cuuint32_t, void*,
    const cuuint64_t*, const cuuint64_t*, const cuuint32_t*, const cuuint32_t*,
    CUtensorMapInterleave, CUtensorMapSwizzle, CUtensorMapL2promotion,
    CUtensorMapFloatOOBfill);

extern "C" void kernel_launch(void* const* d_in, const int* in_sizes, int n_in,
                              void* d_out, int out_size) {
    (void)in_sizes; (void)n_in; (void)out_size;
    const float* x = (const float*)d_in[0];
    void* coeffs   = (void*)d_in[1];
    float* out     = (float*)d_out;

    const int B = 8192, O = 512, K = 4096;

    PFN_encodeTiled enc = nullptr;
    cudaDriverEntryPointQueryResult qres;
    cudaGetDriverEntryPointByVersion("cuTensorMapEncodeTiled", (void**)&enc, 12000,
                                     cudaEnableDefault, &qres);

    CUtensorMap tB;
    {
        cuuint64_t dims[3] = {(cuuint64_t)K, (cuuint64_t)O, 1};
        cuuint64_t str[2]  = {(cuuint64_t)K * 4, (cuuint64_t)K * (cuuint64_t)O * 4};
        cuuint32_t box[3]  = {32, 128, 1};   // per-CTA B half: 128 N-rows
        cuuint32_t es[3]   = {1, 1, 1};
        enc(&tB, CU_TENSOR_MAP_DATA_TYPE_FLOAT32, 3, coeffs, dims, str, box, es,
            CU_TENSOR_MAP_INTERLEAVE_NONE, CU_TENSOR_MAP_SWIZZLE_128B,
            CU_TENSOR_MAP_L2_PROMOTION_L2_128B, CU_TENSOR_MAP_FLOAT_OOB_FILL_NONE);
    }

    cudaFuncSetAttribute(kan_fused_kernel,
                         cudaFuncAttributeMaxDynamicSharedMemorySize, SMEM_TOTAL);
    kan_fused_kernel<<<dim3(B / TILE_M, O / TILE_N, 1), NTHREADS, SMEM_TOTAL>>>(x, tB, out);
}

// round 12
// speedup vs baseline: 3.6227x; 1.0361x over previous
#include <cuda_runtime.h>
#include <cuda.h>
#include <cstdint>
#include <cstddef>

// ============================================================================
// Arch gate: tcgen05 is arch-SPECIFIC (sm_103a). The harness also builds a
// plain compute_103 PTX pass where these mnemonics are illegal — compile an
// empty body there. Only the sm_103a SASS pass gets the real kernel.
// ============================================================================
#if defined(__CUDA_ARCH_FEAT_SM103_ALL) || defined(__CUDA_ARCH_FEAT_SM100_ALL) || \
    (defined(__CUDA_ARCH_SPECIFIC__) && (__CUDA_ARCH_SPECIFIC__ >= 1000)) || \
    (defined(__CUDA_ARCH_FAMILY_SPECIFIC__) && (__CUDA_ARCH_FAMILY_SPECIFIC__ >= 1000))
#define KAN_HAS_TCGEN05 1
#else
#define KAN_HAS_TCGEN05 0
#endif

// ============================================================================
// PTX helpers
// ============================================================================
__device__ __forceinline__ uint32_t smem_u32(const void* p) {
    uint32_t a;
    asm("{ .reg .u64 t; cvta.to.shared.u64 t, %1; cvt.u32.u64 %0, t; }"
        : "=r"(a) : "l"(p));
    return a;
}
__device__ __forceinline__ uint32_t elect_one() {
    uint32_t r;
    asm volatile("{\n\t.reg .pred p;\n\telect.sync _|p, 0xFFFFFFFF;\n\t"
                 "selp.b32 %0, 1, 0, p;\n\t}" : "=r"(r));
    return r;
}
__device__ __forceinline__ uint32_t cluster_rank() {
    uint32_t r;
    asm("mov.u32 %0, %%cluster_ctarank;" : "=r"(r));
    return r;
}

#define MBARRIER_INIT(addr, cnt) \
    asm volatile("mbarrier.init.shared.b64 [%0], %1;" \
                 :: "r"((uint32_t)(addr)), "r"((uint32_t)(cnt)) : "memory")

// Arrive on the mbarrier at the same SMEM offset in cluster CTA `rank`.
#define MBARRIER_ARRIVE_CLUSTER(local_addr, rank) \
    asm volatile( \
        "{\n\t.reg .b32 remAddr;\n\t" \
        "mapa.shared::cluster.u32 remAddr, %0, %1;\n\t" \
        "mbarrier.arrive.shared::cluster.b64 _, [remAddr];\n\t}" \
        :: "r"((uint32_t)(local_addr)), "r"((uint32_t)(rank)) : "memory")

#define MBARRIER_EXPECT_TX(addr, tx) \
    asm volatile("mbarrier.arrive.expect_tx.shared.b64 _, [%0], %1;" \
                 :: "r"((uint32_t)(addr)), "r"((uint32_t)(tx)) : "memory")

#define MBARRIER_WAIT_PARITY(mbar_smem_addr, phase_parity) do { \
    uint32_t _mbar = (uint32_t)(mbar_smem_addr); \
    uint32_t _parity = (uint32_t)(phase_parity); \
    uint32_t _done; \
    asm volatile( \
        "{\n\t.reg .pred p;\n\t" \
        "mbarrier.try_wait.parity.acquire.cta.shared::cta.b64 p, [%1], %2;\n\t" \
        "selp.b32 %0, 1, 0, p;\n\t}" \
        : "=r"(_done) : "r"(_mbar), "r"(_parity) : "memory"); \
    if (!_done) { \
        asm volatile( \
            "{\n\t.reg .pred P1;\n\t" \
            "WAIT_LOOP_%=:\n\t" \
            "mbarrier.try_wait.parity.acquire.cta.shared::cta.b64 P1, [%0], %1, 0x989680;\n\t" \
            "@P1 bra.uni WAIT_DONE_%=;\n\t" \
            "bra.uni WAIT_LOOP_%=;\n\t" \
            "WAIT_DONE_%=:\n\t}" \
            :: "r"(_mbar), "r"(_parity) : "memory"); \
    } \
} while(0)

#define MBARRIER_WAIT_PARITY_RELAXED(mbar_smem_addr, phase_parity) do { \
    uint32_t _mbar = (uint32_t)(mbar_smem_addr); \
    uint32_t _parity = (uint32_t)(phase_parity); \
    uint32_t _done; \
    asm volatile( \
        "{\n\t.reg .pred p;\n\t" \
        "mbarrier.try_wait.parity.relaxed.cta.shared::cta.b64 p, [%1], %2, 0x989680;\n\t" \
        "selp.b32 %0, 1, 0, p;\n\t}" \
        : "=r"(_done) : "r"(_mbar), "r"(_parity) : "memory"); \
    if (!_done) { \
        asm volatile( \
            "{\n\t.reg .pred P1;\n\t" \
            "WAIT_LOOP_%=:\n\t" \
            "mbarrier.try_wait.parity.relaxed.cta.shared::cta.b64 P1, [%0], %1, 0x989680;\n\t" \
            "@P1 bra.uni WAIT_DONE_%=;\n\t" \
            "bra.uni WAIT_LOOP_%=;\n\t" \
            "WAIT_DONE_%=:\n\t}" \
            :: "r"(_mbar), "r"(_parity) : "memory"); \
    } \
} while(0)

// cta_group::2 TMA load: both CTAs execute; complete_tx targets the LEADER
// CTA's barrier (bit 24 of the barrier address cleared).
#define TMA_LOAD_3D_CG2(smem_addr, tensor_map, cx, cy, cz, mbar) \
    asm volatile( \
        "{\n\t.reg .b32 leaderBar;\n\t" \
        "and.b32 leaderBar, %5, 0xFEFFFFFF;\n\t" \
        "cp.async.bulk.tensor.3d.cta_group::2.shared::cluster.global" \
        ".tile.mbarrier::complete_tx::bytes [%0], [%1, {%2, %3, %4}], [leaderBar];\n\t}" \
        :: "r"((uint32_t)(smem_addr)), "l"(tensor_map), \
           "r"((int32_t)(cx)), "r"((int32_t)(cy)), "r"((int32_t)(cz)), \
           "r"((uint32_t)(mbar)) : "memory")

#define STS128Z(addr) \
    asm volatile("st.shared.v4.b32 [%0], {%1, %1, %1, %1};" \
                 :: "r"((uint32_t)(addr)), "r"(0u) : "memory")
#define STS32(addr, v) \
    asm volatile("st.shared.b32 [%0], %1;" \
                 :: "r"((uint32_t)(addr)), "r"((uint32_t)(v)) : "memory")
#define FENCE_PROXY_ASYNC() \
    asm volatile("fence.proxy.async.shared::cta;" ::: "memory")
#define CLUSTER_SYNC() do { \
    asm volatile("barrier.cluster.arrive.aligned;" ::: "memory"); \
    asm volatile("barrier.cluster.wait.aligned;" ::: "memory"); \
} while(0)

#if KAN_HAS_TCGEN05
#define TCGEN05_ALLOC_CG2(smem_result_addr, nCols) \
    asm volatile("tcgen05.alloc.cta_group::2.sync.aligned.shared::cta.b32 [%0], %1;" \
                 :: "r"((uint32_t)(smem_result_addr)), "r"((uint32_t)(nCols)) : "memory")
#define TCGEN05_DEALLOC_CG2(tmem_addr, nCols) \
    asm volatile("tcgen05.dealloc.cta_group::2.sync.aligned.b32 %0, %1;" \
                 :: "r"(tmem_addr), "r"((uint32_t)(nCols)))
#define TCGEN05_RELINQUISH_CG2() \
    asm volatile("tcgen05.relinquish_alloc_permit.cta_group::2.sync.aligned;")
#define TCGEN05_COMMIT_MC_CG2(mbar_smem_addr, mask) \
    asm volatile("tcgen05.commit.cta_group::2.mbarrier::arrive::one.shared::cluster.multicast::cluster.b64 [%0], %1;" \
                 :: "r"((uint32_t)(mbar_smem_addr)), "h"((uint16_t)(mask)) : "memory")
#define TCGEN05_WAIT_LD() \
    asm volatile("tcgen05.wait::ld.sync.aligned;" ::: "memory")
#define TCGEN05_FENCE_AFTER() \
    asm volatile("tcgen05.fence::after_thread_sync;" ::: "memory")

#define TCGEN05_LD_32X32B_X32(r, tmem_addr) \
    asm volatile( \
        "tcgen05.ld.sync.aligned.32x32b.x32.b32 " \
        "{%0, %1, %2, %3, %4, %5, %6, %7, " \
        " %8, %9, %10, %11, %12, %13, %14, %15, " \
        " %16, %17, %18, %19, %20, %21, %22, %23, " \
        " %24, %25, %26, %27, %28, %29, %30, %31}, [%32];" \
        : "=r"((r)[0]),  "=r"((r)[1]),  "=r"((r)[2]),  "=r"((r)[3]), \
          "=r"((r)[4]),  "=r"((r)[5]),  "=r"((r)[6]),  "=r"((r)[7]), \
          "=r"((r)[8]),  "=r"((r)[9]),  "=r"((r)[10]), "=r"((r)[11]), \
          "=r"((r)[12]), "=r"((r)[13]), "=r"((r)[14]), "=r"((r)[15]), \
          "=r"((r)[16]), "=r"((r)[17]), "=r"((r)[18]), "=r"((r)[19]), \
          "=r"((r)[20]), "=r"((r)[21]), "=r"((r)[22]), "=r"((r)[23]), \
          "=r"((r)[24]), "=r"((r)[25]), "=r"((r)[26]), "=r"((r)[27]), \
          "=r"((r)[28]), "=r"((r)[29]), "=r"((r)[30]), "=r"((r)[31]) \
        : "r"(tmem_addr))

// tf32 SS MMA, cta_group::2 (M=256 across the pair). K=8 per dispatch.
__device__ __forceinline__ void mma_tf32_ss_cg2(uint32_t d_tmem, uint64_t a_desc,
                                                uint64_t b_desc, uint32_t idesc, bool acc) {
    uint32_t en = acc ? 1u : 0u;
    asm volatile(
        "{\n\t.reg .pred p;\n\t"
        "setp.ne.u32 p, %5, 0;\n\t"
        "tcgen05.mma.cta_group::2.kind::tf32 [%0], %1, %2, %3, "
        "{%4, %4, %4, %4, %4, %4, %4, %4}, p;\n\t}"
        :: "r"(d_tmem), "l"(a_desc), "l"(b_desc), "r"(idesc), "r"(0u), "r"(en)
        : "memory");
}
#endif  // KAN_HAS_TCGEN05

static constexpr uint64_t SMEM_DESC_BASE_SW128 =
    (uint64_t(2) << 61) | (uint64_t(1) << 46) | (uint64_t(64) << 32) | (uint64_t(1) << 16);
#define MAKE_SMEM_DESC(base_addr) \
    (SMEM_DESC_BASE_SW128 | ((uint64_t)((base_addr) >> 4) & 0x3FFF))

// ============================================================================
// Fused kernel v7 = v6 (57.8us base) + x software-prefetch + deeper A ring.
// Cluster of 2 CTAs covers M=256 x N=256 via cta_group::2; B split N/2 per CTA.
// Warps 0-15: basis -> SMEM A stages (scatter stores, elected waits/arrives,
// x loaded one superstage ahead). Warp 16: TMA B half. Warp 17 (rank0): MMA.
// ============================================================================
static constexpr int TILE_M   = 128;   // per CTA
static constexpr int TILE_N   = 256;   // per cluster (N/2 = 128 per CTA)
static constexpr int KCHUNK   = 32;
static constexpr int NK       = 4096 / KCHUNK;    // 128 MMA chunks
static constexpr int NSUP     = NK / 2;           // 64 A superstages
static constexpr int ASTAGES  = 4;                // deeper ring: absorb jitter
static constexpr int BSTAGES  = 5;
static constexpr int A_SUB    = TILE_M * 128;     // 16 KB per 32-col subtile
static constexpr int A_ST2    = 2 * A_SUB;        // 32 KB superstage
static constexpr int B_ST     = 128 * 128;        // 16 KB per B stage (N/2 rows)

// smem map (byte offsets)
static constexpr int SM_TMEMP  = 0;
static constexpr int SM_FULLA  = 8;                        // 4 x 8B
static constexpr int SM_EMPTYA = SM_FULLA  + ASTAGES * 8;
static constexpr int SM_FULLB  = SM_EMPTYA + ASTAGES * 8;  // 5 x 8B
static constexpr int SM_EMPTYB = SM_FULLB  + BSTAGES * 8;
static constexpr int SM_DONE   = SM_EMPTYB + BSTAGES * 8;
static constexpr int SM_A      = 1024;
static constexpr int SM_B      = SM_A + ASTAGES * A_ST2;   // 132096
static constexpr int SMEM_TOTAL = SM_B + BSTAGES * B_ST;   // 214016

// idesc cg2: c=F32(1<<4), a=TF32(2<<7), b=TF32(2<<10), N=256 (32<<17), M=256 (16<<24)
static constexpr uint32_t IDESC2 =
    (16u << 24) | (32u << 17) | (2u << 10) | (2u << 7) | (1u << 4);

static constexpr int NCOMPUTE_WARPS = 16;
static constexpr int NTHREADS = (NCOMPUTE_WARPS + 2) * 32;  // 576
static constexpr uint16_t MC_MASK = 0x3;

__global__ void __launch_bounds__(NTHREADS, 1) __cluster_dims__(2, 1, 1)
kan_fused_kernel(const float* __restrict__ x,
                 const __grid_constant__ CUtensorMap tma_b,
                 float* __restrict__ out)
{
#if KAN_HAS_TCGEN05
    extern __shared__ __align__(1024) char smem[];
    uint32_t sb = smem_u32(smem);
    int tid = threadIdx.x;
    int wid = tid >> 5, lid = tid & 31;
    int m0 = blockIdx.x * TILE_M;          // per-CTA M origin (pairs share n0)
    int n0 = blockIdx.y * TILE_N;
    uint32_t rank = cluster_rank();        // == blockIdx.x & 1

    if (tid == 0) {
#pragma unroll
        for (int s = 0; s < ASTAGES; s++) {
            MBARRIER_INIT(sb + SM_FULLA  + s * 8, 2 * NCOMPUTE_WARPS); // 1/warp/CTA
            MBARRIER_INIT(sb + SM_EMPTYA + s * 8, 1);    // MC commit, local wait
        }
#pragma unroll
        for (int s = 0; s < BSTAGES; s++) {
            MBARRIER_INIT(sb + SM_FULLB  + s * 8, 1);    // leader expect_tx 32KB
            MBARRIER_INIT(sb + SM_EMPTYB + s * 8, 1);    // MC commit, local wait
        }
        MBARRIER_INIT(sb + SM_DONE, 1);
    }
    if (wid == 17) TCGEN05_ALLOC_CG2(sb + SM_TMEMP, 256);
    __syncthreads();
    CLUSTER_SYNC();   // barriers + alloc visible cluster-wide before traffic
    uint32_t tmem;
    asm volatile("ld.shared.b32 %0, [%1];" : "=r"(tmem) : "r"(sb + SM_TMEMP));

    if (wid < NCOMPUTE_WARPS) {
        // ============ Basis compute warps: fill local A superstages ============
        // 512 threads; thread t: row = t>>2 (0..127), fq = t&3 ->
        // features {2fq, 2fq+1} of the 8 per superstage (subtile = fq>>1).
        int row = tid >> 2;
        int fq  = tid & 3;
        const float* xrow = x + (size_t)(m0 + row) * 512 + fq * 2;
        uint32_t xorc = (uint32_t)(row & 7) << 4;   // SW128 per-row XOR
        uint32_t x16  = xorc & 0x10;
        uint32_t xhi  = xorc & 0x60;
        uint32_t tb = sb + SM_A + (uint32_t)(fq >> 1) * A_SUB + (uint32_t)row * 128;
        uint32_t cb0 = (uint32_t)(fq & 1) * 64;
        uint32_t zb[2] = { tb + (cb0 ^ xhi), tb + ((cb0 + 32) ^ xhi) };

        const float c6 = 1.0f / 6.0f;
        const float L2E2 = 2.8853900817779268f;     // 2*log2(e)
        int sa = 0, pha = 1;
        // Software pipeline: x for superstage ks is loaded during ks-1.
        float2 xv = *reinterpret_cast<const float2*>(xrow);
        for (int ks = 0; ks < NSUP; ks++) {
            float2 xnext;
            if (ks + 1 < NSUP)
                xnext = *reinterpret_cast<const float2*>(xrow + (ks + 1) * 8);
            // Elected wait (per warp, not per thread) -> syncwarp broadcast.
            if (elect_one())
                MBARRIER_WAIT_PARITY(sb + SM_EMPTYA + sa * 8, pha);
            __syncwarp();
            uint32_t soff = (uint32_t)sa * A_ST2;
#pragma unroll
            for (int e = 0; e < 2; e++) {
                float xe = e ? xv.y : xv.x;
                float t, rr;
                asm("ex2.approx.f32 %0, %1;" : "=f"(t) : "f"(xe * L2E2));
                asm("rcp.approx.f32 %0, %1;" : "=f"(rr) : "f"(t + 1.0f));
                float xn = fmaf(-2.0f, rr, 1.0f);   // tanh, err ~1e-7
                float u = (xn + 1.0f) * 5.5f;       // in [0, 11]
                int j = (int)u;
                if (j > 10) j = 10;
                float f = u - (float)j;
                float f2 = f * f, f3 = f2 * f;
                float omf = 1.0f - f;
                uint32_t w[4];
                asm("cvt.rna.tf32.f32 %0, %1;" : "=r"(w[0]) : "f"(omf * omf * omf * c6));
                asm("cvt.rna.tf32.f32 %0, %1;" : "=r"(w[1]) : "f"((3.0f * f3 - 6.0f * f2 + 4.0f) * c6));
                asm("cvt.rna.tf32.f32 %0, %1;" : "=r"(w[2]) : "f"((-3.0f * f3 + 3.0f * f2 + 3.0f * f + 1.0f) * c6));
                asm("cvt.rna.tf32.f32 %0, %1;" : "=r"(w[3]) : "f"(f3 * c6));
                uint32_t zbe = zb[e] + soff;
                STS128Z(zbe + x16);
                STS128Z(zbe + (16u ^ x16));
                int b0 = j - 3;
#pragma unroll
                for (int t4 = 0; t4 < 4; t4++) {
                    int idx = b0 + t4;
                    if ((unsigned)idx < 8u)
                        STS32(zbe + (((uint32_t)idx * 4) ^ x16), w[t4]);
                }
            }
            FENCE_PROXY_ASYNC();
            __syncwarp();
            if (elect_one())
                MBARRIER_ARRIVE_CLUSTER(sb + SM_FULLA + sa * 8, 0);  // leader's fullA
            if (++sa == ASTAGES) { sa = 0; pha ^= 1; }
            xv = xnext;
        }
    } else if (wid == NCOMPUTE_WARPS) {
        // ============ TMA producer: each CTA loads its N/2 B half ============
        if (elect_one()) {
            int s = 0, ph = 1;
            int ncoord = n0 + (int)rank * 128;
            for (int kt = 0; kt < NK; kt++) {
                MBARRIER_WAIT_PARITY_RELAXED(sb + SM_EMPTYB + s * 8, ph);
                if (rank == 0)
                    MBARRIER_EXPECT_TX(sb + SM_FULLB + s * 8, 2 * B_ST);  // both halves
                TMA_LOAD_3D_CG2(sb + SM_B + s * B_ST, &tma_b,
                                kt * KCHUNK, ncoord, 0, sb + SM_FULLB + s * 8);
                if (++s == BSTAGES) { s = 0; ph ^= 1; }
            }
        }
    } else if (rank == 0) {
        // ============ MMA issue warp (leader only) ============
        if (elect_one()) {
            int sa = 0, pa = 0, sbg = 0, pb = 0;
            for (int kt = 0; kt < NK; kt++) {
                if ((kt & 1) == 0) MBARRIER_WAIT_PARITY(sb + SM_FULLA + sa * 8, pa);
                MBARRIER_WAIT_PARITY(sb + SM_FULLB + sbg * 8, pb);
                uint64_t ad = MAKE_SMEM_DESC(sb + SM_A + sa * A_ST2 + (kt & 1) * A_SUB);
                uint64_t bd = MAKE_SMEM_DESC(sb + SM_B + sbg * B_ST);
#pragma unroll
                for (int j = 0; j < 4; j++)
                    mma_tf32_ss_cg2(tmem, ad + 2 * j, bd + 2 * j, IDESC2, (kt > 0) || (j > 0));
                TCGEN05_COMMIT_MC_CG2(sb + SM_EMPTYB + sbg * 8, MC_MASK);
                if (kt & 1) {
                    TCGEN05_COMMIT_MC_CG2(sb + SM_EMPTYA + sa * 8, MC_MASK);
                    if (++sa == ASTAGES) { sa = 0; pa ^= 1; }
                }
                if (++sbg == BSTAGES) { sbg = 0; pb ^= 1; }
            }
            TCGEN05_COMMIT_MC_CG2(sb + SM_DONE, MC_MASK);
        }
    }

    __syncthreads();
    MBARRIER_WAIT_PARITY(sb + SM_DONE, 0);
    TCGEN05_FENCE_AFTER();

    // ---- Epilogue: 8 warps. Warp w: rows (w&3)*32+lid, cols (w>>2)*128.. ----
    if (wid < 8) {
        int coloff = (wid >> 2) * 128;
        float* orow = out + (size_t)(m0 + (wid & 3) * 32 + lid) * 512 + n0 + coloff;
        for (int cb = 0; cb < 128; cb += 32) {
            uint32_t r[32];
            TCGEN05_LD_32X32B_X32(r, tmem + coloff + cb);
            TCGEN05_WAIT_LD();
#pragma unroll
            for (int c = 0; c < 32; c += 4) {
                float4 v = make_float4(__uint_as_float(r[c]),     __uint_as_float(r[c + 1]),
                                       __uint_as_float(r[c + 2]), __uint_as_float(r[c + 3]));
                *reinterpret_cast<float4*>(orow + cb + c) = v;
            }
        }
    }

    __syncthreads();
    if (wid == 17) {
        TCGEN05_RELINQUISH_CG2();
        TCGEN05_DEALLOC_CG2(tmem, 256);
    }
    CLUSTER_SYNC();   // no CTA exits while peer ops may target its smem/TMEM
#else
    // compute_103 (non-'a') PTX fallback pass: never executed on sm_103a.
    (void)x; (void)tma_b; (void)out;
#endif
}

// ============================================================================
// Host launcher
// ============================================================================
typedef CUresult (*PFN_encodeTiled)(
    CUtensorMap*, CUtensorMapDataType, cuuint32_t, void*,
    const cuuint64_t*, const cuuint64_t*, const cuuint32_t*, const cuuint32_t*,
    CUtensorMapInterleave, CUtensorMapSwizzle, CUtensorMapL2promotion,
    CUtensorMapFloatOOBfill);

extern "C" void kernel_launch(void* const* d_in, const int* in_sizes, int n_in,
                              void* d_out, int out_size) {
    (void)in_sizes; (void)n_in; (void)out_size;
    const float* x = (const float*)d_in[0];
    void* coeffs   = (void*)d_in[1];
    float* out     = (float*)d_out;

    const int B = 8192, O = 512, K = 4096;

    PFN_encodeTiled enc = nullptr;
    cudaDriverEntryPointQueryResult qres;
    cudaGetDriverEntryPointByVersion("cuTensorMapEncodeTiled", (void**)&enc, 12000,
                                     cudaEnableDefault, &qres);

    CUtensorMap tB;
    {
        cuuint64_t dims[3] = {(cuuint64_t)K, (cuuint64_t)O, 1};
        cuuint64_t str[2]  = {(cuuint64_t)K * 4, (cuuint64_t)K * (cuuint64_t)O * 4};
        cuuint32_t box[3]  = {32, 128, 1};   // per-CTA B half: 128 N-rows
        cuuint32_t es[3]   = {1, 1, 1};
        enc(&tB, CU_TENSOR_MAP_DATA_TYPE_FLOAT32, 3, coeffs, dims, str, box, es,
            CU_TENSOR_MAP_INTERLEAVE_NONE, CU_TENSOR_MAP_SWIZZLE_128B,
            CU_TENSOR_MAP_L2_PROMOTION_L2_128B, CU_TENSOR_MAP_FLOAT_OOB_FILL_NONE);
    }

    cudaFuncSetAttribute(kan_fused_kernel,
                         cudaFuncAttributeMaxDynamicSharedMemorySize, SMEM_TOTAL);
    kan_fused_kernel<<<dim3(B / TILE_M, O / TILE_N, 1), NTHREADS, SMEM_TOTAL>>>(x, tB, out);
}